// round 6
// baseline (speedup 1.0000x reference)
#include <cuda_runtime.h>
#include <cstdint>

#define BATCH 16384
#define NEG 5
#define ROWS 7                                   // u, v, 5 negs
#define WARPS_PER_BLOCK 4
#define THREADS (WARPS_PER_BLOCK * 32)           // 128
#define ELEMS_PER_WARP 2
#define ELEMS_PER_BLOCK (WARPS_PER_BLOCK * ELEMS_PER_WARP)   // 8
#define NBLOCKS (BATCH / ELEMS_PER_BLOCK)        // 2048

__device__ float g_partials[NBLOCKS];
__device__ unsigned int g_count;                 // zero-init; last block resets

__device__ __forceinline__ float logsig(float x) {
    return fminf(x, 0.0f) - log1pf(expf(-fabsf(x)));
}

__device__ __forceinline__ float score_pair(const float4* st, int lane,
                                            float& neg_out) {
    // st points at stage[warp][e][0]
    const float4 u  = st[0 * 32 + lane];
    const float4 v  = st[1 * 32 + lane];
    const float4 w0 = st[2 * 32 + lane];
    const float4 w1 = st[3 * 32 + lane];
    const float4 w2 = st[4 * 32 + lane];
    const float4 w3 = st[5 * 32 + lane];
    const float4 w4 = st[6 * 32 + lane];

    float4 ns;
    ns.x = w0.x + w1.x + w2.x + w3.x + w4.x;
    ns.y = w0.y + w1.y + w2.y + w3.y + w4.y;
    ns.z = w0.z + w1.z + w2.z + w3.z + w4.z;
    ns.w = w0.w + w1.w + w2.w + w3.w + w4.w;

    neg_out = u.x * ns.x + u.y * ns.y + u.z * ns.z + u.w * ns.w;
    return u.x * v.x + u.y * v.y + u.z * v.z + u.w * v.w;
}

__global__ void __launch_bounds__(THREADS)
sg_fused(const float* __restrict__ emb,
         const int* __restrict__ centers,
         const int* __restrict__ contexts,
         const int* __restrict__ negs,
         float* __restrict__ out) {
    // [warp][elem][row][lane] float4 : 4*2*7*512B = 28 KB (static, <48KB)
    __shared__ __align__(16) float4 stage[WARPS_PER_BLOCK][ELEMS_PER_WARP][ROWS][32];
    __shared__ float sm[WARPS_PER_BLOCK];
    __shared__ bool is_last;

    const int lane = threadIdx.x & 31;
    const int warp = threadIdx.x >> 5;
    const int b0 = blockIdx.x * ELEMS_PER_BLOCK + warp * ELEMS_PER_WARP;
    const int b1 = b0 + 1;

    // Divergent index fetch: lanes 0..6 for element 0, lanes 16..22 for element 1.
    int idx = 0;
    {
        int l = lane & 15;
        int b = (lane < 16) ? b0 : b1;
        if (lane < 7 || (lane >= 16 && lane < 23)) {
            if (l == 0)      idx = centers[b];
            else if (l == 1) idx = contexts[b];
            else             idx = negs[b * NEG + (l - 2)];
        }
    }

    const float4* e4 = reinterpret_cast<const float4*>(emb);

    // Element 0 rows -> group, element 1 rows -> group (14 LDGSTS in flight/warp).
    #pragma unroll
    for (int r = 0; r < ROWS; r++) {
        int row = __shfl_sync(0xffffffffu, idx, r);
        const float4* src = e4 + (size_t)row * 32 + lane;
        uint32_t dst = (uint32_t)__cvta_generic_to_shared(&stage[warp][0][r][lane]);
        asm volatile("cp.async.cg.shared.global [%0], [%1], 16;\n" :: "r"(dst), "l"(src));
    }
    asm volatile("cp.async.commit_group;\n");
    #pragma unroll
    for (int r = 0; r < ROWS; r++) {
        int row = __shfl_sync(0xffffffffu, idx, 16 + r);
        const float4* src = e4 + (size_t)row * 32 + lane;
        uint32_t dst = (uint32_t)__cvta_generic_to_shared(&stage[warp][1][r][lane]);
        asm volatile("cp.async.cg.shared.global [%0], [%1], 16;\n" :: "r"(dst), "l"(src));
    }
    asm volatile("cp.async.commit_group;\n");

    // Compute element 0 while element 1's rows are still in flight.
    asm volatile("cp.async.wait_group 1;\n" ::: "memory");
    __syncwarp();
    float neg0, pos0 = score_pair(&stage[warp][0][0][0], lane, neg0);

    asm volatile("cp.async.wait_group 0;\n" ::: "memory");
    __syncwarp();
    float neg1, pos1 = score_pair(&stage[warp][1][0][0], lane, neg1);

    #pragma unroll
    for (int o = 16; o > 0; o >>= 1) {
        pos0 += __shfl_xor_sync(0xffffffffu, pos0, o);
        neg0 += __shfl_xor_sync(0xffffffffu, neg0, o);
        pos1 += __shfl_xor_sync(0xffffffffu, pos1, o);
        neg1 += __shfl_xor_sync(0xffffffffu, neg1, o);
    }

    if (lane == 0)
        sm[warp] = (logsig(pos0) + logsig(-neg0)) +
                   (logsig(pos1) + logsig(-neg1));
    __syncthreads();

    if (threadIdx.x == 0) {
        float s = 0.0f;
        #pragma unroll
        for (int i = 0; i < WARPS_PER_BLOCK; i++) s += sm[i];
        g_partials[blockIdx.x] = s;
        __threadfence();
        unsigned int t = atomicAdd(&g_count, 1u);
        is_last = (t == NBLOCKS - 1);
    }
    __syncthreads();

    // Last block: deterministic fixed-order reduction of 2048 partials.
    if (is_last) {
        __shared__ float red[THREADS];
        float s = 0.0f;
        #pragma unroll
        for (int i = 0; i < NBLOCKS / THREADS; i++)     // 16 per thread
            s += g_partials[threadIdx.x + i * THREADS];
        red[threadIdx.x] = s;
        __syncthreads();
        #pragma unroll
        for (int o = THREADS / 2; o > 0; o >>= 1) {
            if (threadIdx.x < o) red[threadIdx.x] += red[threadIdx.x + o];
            __syncthreads();
        }
        if (threadIdx.x == 0) {
            out[0] = -red[0];
            g_count = 0;   // reset for next graph replay (determinism)
        }
    }
}

extern "C" void kernel_launch(void* const* d_in, const int* in_sizes, int n_in,
                              void* d_out, int out_size) {
    const float* emb      = (const float*)d_in[0];
    const int*   centers  = (const int*)  d_in[1];
    const int*   contexts = (const int*)  d_in[2];
    const int*   negs     = (const int*)  d_in[3];
    float*       out      = (float*)d_out;

    sg_fused<<<NBLOCKS, THREADS>>>(emb, centers, contexts, negs, out);
}

// round 7
// speedup vs baseline: 1.0226x; 1.0226x over previous
#include <cuda_runtime.h>
#include <cstdint>

#define BATCH 16384
#define NEG 5
#define ROWS 7                                   // u, v, 5 negs
#define WARPS_PER_BLOCK 4
#define THREADS (WARPS_PER_BLOCK * 32)           // 128
#define ELEMS_PER_WARP 2
#define ELEMS_PER_BLOCK (WARPS_PER_BLOCK * ELEMS_PER_WARP)   // 8
#define NBLOCKS (BATCH / ELEMS_PER_BLOCK)        // 2048

__device__ float g_partials[NBLOCKS];
__device__ unsigned int g_count;                 // zero-init; last block resets

__device__ __forceinline__ float logsig(float x) {
    return fminf(x, 0.0f) - log1pf(expf(-fabsf(x)));
}

__device__ __forceinline__ float score_pair(const float4* st, int lane,
                                            float& neg_out) {
    // st points at stage[warp][e][0]
    const float4 u  = st[0 * 32 + lane];
    const float4 v  = st[1 * 32 + lane];
    const float4 w0 = st[2 * 32 + lane];
    const float4 w1 = st[3 * 32 + lane];
    const float4 w2 = st[4 * 32 + lane];
    const float4 w3 = st[5 * 32 + lane];
    const float4 w4 = st[6 * 32 + lane];

    float4 ns;
    ns.x = w0.x + w1.x + w2.x + w3.x + w4.x;
    ns.y = w0.y + w1.y + w2.y + w3.y + w4.y;
    ns.z = w0.z + w1.z + w2.z + w3.z + w4.z;
    ns.w = w0.w + w1.w + w2.w + w3.w + w4.w;

    neg_out = u.x * ns.x + u.y * ns.y + u.z * ns.z + u.w * ns.w;
    return u.x * v.x + u.y * v.y + u.z * v.z + u.w * v.w;
}

__global__ void __launch_bounds__(THREADS)
sg_fused(const float* __restrict__ emb,
         const int* __restrict__ centers,
         const int* __restrict__ contexts,
         const int* __restrict__ negs,
         float* __restrict__ out) {
    // [warp][elem][row][lane] float4 : 4*2*7*512B = 28 KB (static, <48KB)
    __shared__ __align__(16) float4 stage[WARPS_PER_BLOCK][ELEMS_PER_WARP][ROWS][32];
    __shared__ float sm[WARPS_PER_BLOCK];
    __shared__ bool is_last;

    const int lane = threadIdx.x & 31;
    const int warp = threadIdx.x >> 5;
    const int b0 = blockIdx.x * ELEMS_PER_BLOCK + warp * ELEMS_PER_WARP;
    const int b1 = b0 + 1;

    // Divergent index fetch: lanes 0..6 for element 0, lanes 16..22 for element 1.
    int idx = 0;
    {
        int l = lane & 15;
        int b = (lane < 16) ? b0 : b1;
        if (lane < 7 || (lane >= 16 && lane < 23)) {
            if (l == 0)      idx = centers[b];
            else if (l == 1) idx = contexts[b];
            else             idx = negs[b * NEG + (l - 2)];
        }
    }

    const float4* e4 = reinterpret_cast<const float4*>(emb);

    // Element 0 rows -> group, element 1 rows -> group (14 LDGSTS in flight/warp).
    #pragma unroll
    for (int r = 0; r < ROWS; r++) {
        int row = __shfl_sync(0xffffffffu, idx, r);
        const float4* src = e4 + (size_t)row * 32 + lane;
        uint32_t dst = (uint32_t)__cvta_generic_to_shared(&stage[warp][0][r][lane]);
        asm volatile("cp.async.cg.shared.global [%0], [%1], 16;\n" :: "r"(dst), "l"(src));
    }
    asm volatile("cp.async.commit_group;\n");
    #pragma unroll
    for (int r = 0; r < ROWS; r++) {
        int row = __shfl_sync(0xffffffffu, idx, 16 + r);
        const float4* src = e4 + (size_t)row * 32 + lane;
        uint32_t dst = (uint32_t)__cvta_generic_to_shared(&stage[warp][1][r][lane]);
        asm volatile("cp.async.cg.shared.global [%0], [%1], 16;\n" :: "r"(dst), "l"(src));
    }
    asm volatile("cp.async.commit_group;\n");

    // Compute element 0 while element 1's rows are still in flight.
    asm volatile("cp.async.wait_group 1;\n" ::: "memory");
    __syncwarp();
    float neg0, pos0 = score_pair(&stage[warp][0][0][0], lane, neg0);

    asm volatile("cp.async.wait_group 0;\n" ::: "memory");
    __syncwarp();
    float neg1, pos1 = score_pair(&stage[warp][1][0][0], lane, neg1);

    #pragma unroll
    for (int o = 16; o > 0; o >>= 1) {
        pos0 += __shfl_xor_sync(0xffffffffu, pos0, o);
        neg0 += __shfl_xor_sync(0xffffffffu, neg0, o);
        pos1 += __shfl_xor_sync(0xffffffffu, pos1, o);
        neg1 += __shfl_xor_sync(0xffffffffu, neg1, o);
    }

    if (lane == 0)
        sm[warp] = (logsig(pos0) + logsig(-neg0)) +
                   (logsig(pos1) + logsig(-neg1));
    __syncthreads();

    if (threadIdx.x == 0) {
        float s = 0.0f;
        #pragma unroll
        for (int i = 0; i < WARPS_PER_BLOCK; i++) s += sm[i];
        g_partials[blockIdx.x] = s;
        __threadfence();
        unsigned int t = atomicAdd(&g_count, 1u);
        is_last = (t == NBLOCKS - 1);
    }
    __syncthreads();

    // Last block: deterministic fixed-order reduction of 2048 partials.
    if (is_last) {
        __shared__ float red[THREADS];
        float s = 0.0f;
        #pragma unroll
        for (int i = 0; i < NBLOCKS / THREADS; i++)     // 16 per thread
            s += g_partials[threadIdx.x + i * THREADS];
        red[threadIdx.x] = s;
        __syncthreads();
        #pragma unroll
        for (int o = THREADS / 2; o > 0; o >>= 1) {
            if (threadIdx.x < o) red[threadIdx.x] += red[threadIdx.x + o];
            __syncthreads();
        }
        if (threadIdx.x == 0) {
            out[0] = -red[0];
            g_count = 0;   // reset for next graph replay (determinism)
        }
    }
}

extern "C" void kernel_launch(void* const* d_in, const int* in_sizes, int n_in,
                              void* d_out, int out_size) {
    const float* emb      = (const float*)d_in[0];
    const int*   centers  = (const int*)  d_in[1];
    const int*   contexts = (const int*)  d_in[2];
    const int*   negs     = (const int*)  d_in[3];
    float*       out      = (float*)d_out;

    sg_fused<<<NBLOCKS, THREADS>>>(emb, centers, contexts, negs, out);
}